// round 1
// baseline (speedup 1.0000x reference)
#include <cuda_runtime.h>

#define BM 64
#define BN 64
#define BK 16
#define TPB 256

// -------- scratch (device globals: allocation-free) --------
__device__ float g_s1[31500000];   // max 31,488,000 (conv W2 out)
__device__ float g_s2[22200000];   // max 22,118,400 (lin Wl2 out)
__device__ float g_s3[50400000];   // max 50,380,800 (conv W3 out)

// ===================== Linear (Semi_Linear) GEMM =====================
// out[m, n] = sum_k A[m*K + k] * W[n*K + k] + bias[n]   (optional ReLU)
template<bool RELU>
__global__ __launch_bounds__(TPB)
void lin_kernel(const float* __restrict__ A, const float* __restrict__ Wt,
                const float* __restrict__ bias, float* __restrict__ out,
                int M, int N, int K)
{
    __shared__ float As[BK][BM];
    __shared__ float Bs[BK][BN];
    const int t  = threadIdx.x;
    const int m0 = blockIdx.x * BM;
    const int n0 = blockIdx.y * BN;
    const int tx = t & 15;        // N direction
    const int ty = t >> 4;        // M direction

    float acc[4][4];
    #pragma unroll
    for (int i = 0; i < 4; i++)
        #pragma unroll
        for (int j = 0; j < 4; j++) acc[i][j] = 0.f;

    for (int k0 = 0; k0 < K; k0 += BK) {
        // A tile: row-major sweep (coalesced along contiguous K)
        #pragma unroll
        for (int j = 0; j < 4; j++) {
            int p   = t + j * TPB;
            int col = p & (BK - 1);
            int row = p >> 4;
            int gm = m0 + row, gk = k0 + col;
            float v = 0.f;
            if (gm < M && gk < K) v = A[(size_t)gm * K + gk];
            As[col][row] = v;
        }
        // W tile: weights row-major [N, K]
        #pragma unroll
        for (int j = 0; j < 4; j++) {
            int p  = t + j * TPB;
            int kk = p & (BK - 1);
            int nn = p >> 4;
            int gn = n0 + nn, gk = k0 + kk;
            float v = 0.f;
            if (gn < N && gk < K) v = Wt[(size_t)gn * K + gk];
            Bs[kk][nn] = v;
        }
        __syncthreads();
        #pragma unroll
        for (int k = 0; k < BK; k++) {
            float4 a4 = *reinterpret_cast<const float4*>(&As[k][ty * 4]);
            float4 b4 = *reinterpret_cast<const float4*>(&Bs[k][tx * 4]);
            float a[4] = {a4.x, a4.y, a4.z, a4.w};
            float b[4] = {b4.x, b4.y, b4.z, b4.w};
            #pragma unroll
            for (int i = 0; i < 4; i++)
                #pragma unroll
                for (int j = 0; j < 4; j++)
                    acc[i][j] = fmaf(a[i], b[j], acc[i][j]);
        }
        __syncthreads();
    }

    #pragma unroll
    for (int i = 0; i < 4; i++) {
        int gm = m0 + ty * 4 + i;
        if (gm >= M) continue;
        #pragma unroll
        for (int j = 0; j < 4; j++) {
            int gn = n0 + tx * 4 + j;
            if (gn >= N) continue;
            float v = acc[i][j] + bias[gn];
            if (RELU) v = fmaxf(v, 0.f);
            out[(size_t)gm * N + gn] = v;
        }
    }
}

// ===================== H-conv as implicit GEMM =====================
// in : [B, I, Hin, W], weight: [O, I, KH] (row-major => [O, K] with K = I*KH)
// out: [B, O, Hout, W], Hout = Hin + 2*pad - KH + 1
// M index m = (b*Hout + h)*W + w  (w fastest -> coalesced gathers)
// ACC: out[idx] += (conv + bias)   (residual fold)
template<int KH, bool ACC>
__global__ __launch_bounds__(TPB)
void conv_kernel(const float* __restrict__ In, const float* __restrict__ Wt,
                 const float* __restrict__ bias, float* __restrict__ out,
                 int B, int I, int Hin, int W, int O, int pad)
{
    const int Hout = Hin + 2 * pad - KH + 1;
    const int M = B * Hout * W;
    const int K = I * KH;

    __shared__ float As[BK][BM];
    __shared__ float Bs[BK][BN];
    const int t  = threadIdx.x;
    const int m0 = blockIdx.x * BM;
    const int n0 = blockIdx.y * BN;
    const int tx = t & 15;
    const int ty = t >> 4;

    // A-loader: column-major sweep -> row fixed per thread (constant decompose)
    const int lrow = t & (BM - 1);
    const int gm_l = m0 + lrow;
    int lb = 0, lh = 0, lw = 0;
    bool mvalid = gm_l < M;
    if (mvalid) {
        lw = gm_l % W;
        int tmp = gm_l / W;
        lh = tmp % Hout;
        lb = tmp / Hout;
    }
    const size_t lbase = (size_t)lb * I * Hin * W + lw;

    float acc[4][4];
    #pragma unroll
    for (int i = 0; i < 4; i++)
        #pragma unroll
        for (int j = 0; j < 4; j++) acc[i][j] = 0.f;

    for (int k0 = 0; k0 < K; k0 += BK) {
        // A tile (gather)
        #pragma unroll
        for (int j = 0; j < 4; j++) {
            int col = (t >> 6) + j * 4;        // 0..15
            int gk  = k0 + col;
            float v = 0.f;
            if (mvalid && gk < K) {
                int i  = gk / KH;
                int kh = gk - i * KH;
                int hi = lh + kh - pad;
                if (hi >= 0 && hi < Hin)
                    v = In[lbase + (size_t)(i * Hin + hi) * W];
            }
            As[col][lrow] = v;
        }
        // W tile
        #pragma unroll
        for (int j = 0; j < 4; j++) {
            int p  = t + j * TPB;
            int kk = p & (BK - 1);
            int nn = p >> 4;
            int gn = n0 + nn, gk = k0 + kk;
            float v = 0.f;
            if (gn < O && gk < K) v = Wt[(size_t)gn * K + gk];
            Bs[kk][nn] = v;
        }
        __syncthreads();
        #pragma unroll
        for (int k = 0; k < BK; k++) {
            float4 a4 = *reinterpret_cast<const float4*>(&As[k][ty * 4]);
            float4 b4 = *reinterpret_cast<const float4*>(&Bs[k][tx * 4]);
            float a[4] = {a4.x, a4.y, a4.z, a4.w};
            float b[4] = {b4.x, b4.y, b4.z, b4.w};
            #pragma unroll
            for (int i = 0; i < 4; i++)
                #pragma unroll
                for (int j = 0; j < 4; j++)
                    acc[i][j] = fmaf(a[i], b[j], acc[i][j]);
        }
        __syncthreads();
    }

    #pragma unroll
    for (int i = 0; i < 4; i++) {
        int gm = m0 + ty * 4 + i;
        if (gm >= M) continue;
        int w  = gm % W;
        int tmp = gm / W;
        int h  = tmp % Hout;
        int b  = tmp / Hout;
        #pragma unroll
        for (int j = 0; j < 4; j++) {
            int gn = n0 + tx * 4 + j;
            if (gn >= O) continue;
            size_t idx = (((size_t)b * O + gn) * Hout + h) * W + w;
            float v = acc[i][j] + bias[gn];
            if (ACC) out[idx] = out[idx] + v;
            else     out[idx] = v;
        }
    }
}

// ===================== host-side helpers =====================
static inline void run_lin(const float* A, const float* W, const float* b,
                           float* out, int M, int N, int K, bool relu)
{
    dim3 grid((M + BM - 1) / BM, (N + BN - 1) / BN);
    if (relu) lin_kernel<true ><<<grid, TPB>>>(A, W, b, out, M, N, K);
    else      lin_kernel<false><<<grid, TPB>>>(A, W, b, out, M, N, K);
}

static inline void run_conv(const float* In, const float* W, const float* b,
                            float* out, int B, int I, int Hin, int Wd, int O,
                            int pad, int KH, bool acc)
{
    int Hout = Hin + 2 * pad - KH + 1;
    int M = B * Hout * Wd;
    dim3 grid((M + BM - 1) / BM, (O + BN - 1) / BN);
    if (KH == 3) {
        if (acc) conv_kernel<3, true ><<<grid, TPB>>>(In, W, b, out, B, I, Hin, Wd, O, pad);
        else     conv_kernel<3, false><<<grid, TPB>>>(In, W, b, out, B, I, Hin, Wd, O, pad);
    } else if (KH == 2) {
        if (acc) conv_kernel<2, true ><<<grid, TPB>>>(In, W, b, out, B, I, Hin, Wd, O, pad);
        else     conv_kernel<2, false><<<grid, TPB>>>(In, W, b, out, B, I, Hin, Wd, O, pad);
    } else {
        if (acc) conv_kernel<1, true ><<<grid, TPB>>>(In, W, b, out, B, I, Hin, Wd, O, pad);
        else     conv_kernel<1, false><<<grid, TPB>>>(In, W, b, out, B, I, Hin, Wd, O, pad);
    }
}

extern "C" void kernel_launch(void* const* d_in, const int* in_sizes, int n_in,
                              void* d_out, int out_size)
{
    const float* x   = (const float*)d_in[0];
    const float* W0a = (const float*)d_in[1];  const float* b0a = (const float*)d_in[2];
    const float* Wl0 = (const float*)d_in[3];  const float* bl0 = (const float*)d_in[4];
    const float* W0b = (const float*)d_in[5];  const float* b0b = (const float*)d_in[6];
    const float* Wr0 = (const float*)d_in[7];  const float* br0 = (const float*)d_in[8];
    const float* W0c = (const float*)d_in[9];  const float* b0c = (const float*)d_in[10];
    const float* W1  = (const float*)d_in[11]; const float* b1  = (const float*)d_in[12];
    const float* Wl1 = (const float*)d_in[13]; const float* bl1 = (const float*)d_in[14];
    const float* W2  = (const float*)d_in[15]; const float* b2  = (const float*)d_in[16];
    const float* Wra = (const float*)d_in[17]; const float* bra = (const float*)d_in[18];
    const float* Wa  = (const float*)d_in[19]; const float* ba  = (const float*)d_in[20];
    const float* W3  = (const float*)d_in[21]; const float* b3  = (const float*)d_in[22];
    const float* Wl2 = (const float*)d_in[23]; const float* bl2 = (const float*)d_in[24];
    const float* W4  = (const float*)d_in[25]; const float* b4  = (const float*)d_in[26];
    const float* Wrb = (const float*)d_in[27]; const float* brb = (const float*)d_in[28];
    const float* Wb  = (const float*)d_in[29]; const float* bb  = (const float*)d_in[30];

    float* out = (float*)d_out;

    float *S1, *S2, *S3;
    cudaGetSymbolAddress((void**)&S1, g_s1);
    cudaGetSymbolAddress((void**)&S2, g_s2);
    cudaGetSymbolAddress((void**)&S3, g_s3);

    const int B = 1024;

    // ---------------- block 0 ----------------
    // 1. t0 = conv(x, W0a, pad=1):            [B,5,5,127] -> S1
    run_conv(x,  W0a, b0a, S1, B, 1, 5, 127, 5, 1, 3, false);
    // 2. t1 = relu(lin(t0, Wl0)):             [B,5,5,81]  -> S2
    run_lin(S1, Wl0, bl0, S2, B * 5 * 5, 81, 127, true);
    // 3. t2 = conv(t1, W0b, pad=1):           [B,25,5,81] -> S3
    run_conv(S2, W0b, b0b, S3, B, 5, 5, 81, 25, 1, 3, false);
    // 4. t3 = lin(x, Wr0):                    [B,1,5,81]  -> S1
    run_lin(x,  Wr0, br0, S1, B * 1 * 5, 81, 127, false);
    // 5. x1 = t2 + conv(t3, W0c, 1x1):        S3 += conv  (x1 = S3)
    run_conv(S1, W0c, b0c, S3, B, 1, 5, 81, 25, 0, 1, true);

    // ---------------- block 1 ----------------
    // 6. z = conv(x1, W1, pad=1):             [B,75,5,81] -> S1
    run_conv(S3, W1, b1, S1, B, 25, 5, 81, 75, 1, 3, false);
    // 7. z = relu(lin(z, Wl1)):               [B,75,5,41] -> S2
    run_lin(S1, Wl1, bl1, S2, B * 75 * 5, 41, 81, true);
    // 8. z = conv(z, W2, pad=1):              [B,150,5,41] -> S1
    run_conv(S2, W2, b2, S1, B, 75, 5, 41, 150, 1, 3, false);
    // 9. y = lin(x1, Wra):                    [B,25,5,41] -> S2
    run_lin(S3, Wra, bra, S2, B * 25 * 5, 41, 81, false);
    // 10. x2 = z + conv(y, Wa, 1x1):          S1 += conv  (x2 = S1)
    run_conv(S2, Wa, ba, S1, B, 25, 5, 41, 150, 0, 1, true);

    // ---------------- block 2 ----------------
    // 11. z = conv(x2, W3, pad=0, kh=2):      [B,300,4,41] -> S3
    run_conv(S1, W3, b3, S3, B, 150, 5, 41, 300, 0, 2, false);
    // 12. z = relu(lin(z, Wl2)):              [B,300,4,18] -> S2
    run_lin(S3, Wl2, bl2, S2, B * 300 * 4, 18, 41, true);
    // 13. z = conv(z, W4, pad=0, kh=2):       [B,512,3,18] -> d_out
    run_conv(S2, W4, b4, out, B, 300, 4, 18, 512, 0, 2, false);
    // 14. y = lin(x2, Wrb):                   [B,150,5,18] -> S3
    run_lin(S1, Wrb, brb, S3, B * 150 * 5, 18, 41, false);
    // 15. out += conv(y, Wb, pad=0, kh=3):    [B,512,3,18] accumulate
    run_conv(S3, Wb, bb, out, B, 150, 5, 18, 512, 0, 3, true);
}

// round 2
// speedup vs baseline: 1.4900x; 1.4900x over previous
#include <cuda_runtime.h>

#define BK 16

// -------- scratch (device globals: allocation-free) --------
__device__ float g_s1[31500000];
__device__ float g_s2[22200000];
__device__ float g_s3[50400000];

// =====================================================================
// Shared tiled-GEMM skeleton: 256 threads, TM=8 x TN=4 micro-tile,
// double-buffered smem with register staging (1 sync per BK step).
// Config A: BM=128, BN=64   (wide N)
// Config B: BM=256, BN=32   (narrow N)
// =====================================================================

// ===================== Linear (Semi_Linear) GEMM =====================
// out[m, n] = sum_k A[m*K + k] * W[n*K + k] + bias[n]   (optional ReLU)
template<int BM_, int BN_, bool RELU>
__global__ __launch_bounds__(256, 2)
void lin_kernel(const float* __restrict__ A, const float* __restrict__ Wt,
                const float* __restrict__ bias, float* __restrict__ out,
                int M, int N, int K)
{
    constexpr int TM = 8, TN = 4;
    constexpr int GROUPS = 256 / BM_;      // col-groups in A loader (2 or 1)
    constexpr int CPT    = BK / GROUPS;    // K-cols per thread (8 or 16)
    constexpr int LB     = BN_ * BK / 256; // B elems per thread (4 or 2)
    constexpr int NT     = BN_ / TN;       // threads along N (16 or 8)

    __shared__ __align__(16) float As[2][BK][BM_];
    __shared__ __align__(16) float Bs[2][BK][BN_];

    const int t  = threadIdx.x;
    const int m0 = blockIdx.x * BM_;
    const int n0 = blockIdx.y * BN_;
    const int tx = t % NT;
    const int ty = t / NT;

    // A loader: one fixed M-row per thread, CPT contiguous K elems
    const int arow  = t % BM_;
    const int acol0 = (t / BM_) * CPT;
    const int gm_l  = m0 + arow;
    const bool mvalid = gm_l < M;
    const float* Arow = A + (size_t)gm_l * K;

    float regA[CPT], regB[LB];
    float acc[TM][TN];
    #pragma unroll
    for (int i = 0; i < TM; i++)
        #pragma unroll
        for (int j = 0; j < TN; j++) acc[i][j] = 0.f;

    auto loadA = [&](int k0) {
        #pragma unroll
        for (int j = 0; j < CPT; j++) {
            int gk = k0 + acol0 + j;
            regA[j] = (mvalid && gk < K) ? Arow[gk] : 0.f;
        }
    };
    auto loadB = [&](int k0) {
        #pragma unroll
        for (int j = 0; j < LB; j++) {
            int p  = t + j * 256;
            int kk = p & (BK - 1);
            int nn = p >> 4;
            int gn = n0 + nn, gk = k0 + kk;
            regB[j] = (gn < N && gk < K) ? Wt[(size_t)gn * K + gk] : 0.f;
        }
    };
    auto store = [&](int buf) {
        #pragma unroll
        for (int j = 0; j < CPT; j++) As[buf][acol0 + j][arow] = regA[j];
        #pragma unroll
        for (int j = 0; j < LB; j++) {
            int p = t + j * 256;
            Bs[buf][p & (BK - 1)][p >> 4] = regB[j];
        }
    };
    auto compute = [&](int buf) {
        #pragma unroll
        for (int k = 0; k < BK; k++) {
            float a[TM], b[TN];
            *(float4*)&a[0] = *(const float4*)&As[buf][k][ty * TM];
            *(float4*)&a[4] = *(const float4*)&As[buf][k][ty * TM + 4];
            *(float4*)&b[0] = *(const float4*)&Bs[buf][k][tx * TN];
            #pragma unroll
            for (int i = 0; i < TM; i++)
                #pragma unroll
                for (int j = 0; j < TN; j++)
                    acc[i][j] = fmaf(a[i], b[j], acc[i][j]);
        }
    };

    loadA(0); loadB(0);
    store(0);
    __syncthreads();
    int buf = 0;
    for (int k0 = 0; k0 < K; k0 += BK) {
        bool has_next = (k0 + BK) < K;
        if (has_next) { loadA(k0 + BK); loadB(k0 + BK); }
        compute(buf);
        if (has_next) {
            store(buf ^ 1);
            __syncthreads();
            buf ^= 1;
        }
    }

    #pragma unroll
    for (int i = 0; i < TM; i++) {
        int gm = m0 + ty * TM + i;
        if (gm >= M) continue;
        #pragma unroll
        for (int j = 0; j < TN; j++) {
            int gn = n0 + tx * TN + j;
            if (gn >= N) continue;
            float v = acc[i][j] + bias[gn];
            if (RELU) v = fmaxf(v, 0.f);
            out[(size_t)gm * N + gn] = v;
        }
    }
}

// ===================== H-conv as implicit GEMM =====================
// in : [B, I, Hin, W], weight: [O, I, KH] (row-major => [O, K], K = I*KH)
// out: [B, O, Hout, W];  ACC: out[idx] += (conv + bias)
template<int BM_, int BN_, int KH, bool ACC>
__global__ __launch_bounds__(256, 2)
void conv_kernel(const float* __restrict__ In, const float* __restrict__ Wt,
                 const float* __restrict__ bias, float* __restrict__ out,
                 int B, int I, int Hin, int W, int O, int pad)
{
    constexpr int TM = 8, TN = 4;
    constexpr int GROUPS = 256 / BM_;
    constexpr int CPT    = BK / GROUPS;
    constexpr int LB     = BN_ * BK / 256;
    constexpr int NT     = BN_ / TN;

    const int Hout = Hin + 2 * pad - KH + 1;
    const int M = B * Hout * W;
    const int K = I * KH;

    __shared__ __align__(16) float As[2][BK][BM_];
    __shared__ __align__(16) float Bs[2][BK][BN_];

    const int t  = threadIdx.x;
    const int m0 = blockIdx.x * BM_;
    const int n0 = blockIdx.y * BN_;
    const int tx = t % NT;
    const int ty = t / NT;

    // A loader: fixed M-row per thread (im2col gather)
    const int arow  = t % BM_;
    const int acol0 = (t / BM_) * CPT;
    const int gm_l  = m0 + arow;
    const bool mvalid = gm_l < M;
    int lh = 0; size_t lbase = 0;
    if (mvalid) {
        int lw  = gm_l % W;
        int tmp = gm_l / W;
        lh = tmp % Hout;
        int lb = tmp / Hout;
        lbase = (size_t)lb * I * Hin * W + lw;
    }

    float regA[CPT], regB[LB];
    float acc[TM][TN];
    #pragma unroll
    for (int i = 0; i < TM; i++)
        #pragma unroll
        for (int j = 0; j < TN; j++) acc[i][j] = 0.f;

    auto loadA = [&](int k0) {
        #pragma unroll
        for (int j = 0; j < CPT; j++) {
            int gk = k0 + acol0 + j;
            float v = 0.f;
            if (mvalid && gk < K) {
                int ii = gk / KH;
                int kh = gk - ii * KH;
                int hi = lh + kh - pad;
                if (hi >= 0 && hi < Hin)
                    v = In[lbase + (size_t)(ii * Hin + hi) * W];
            }
            regA[j] = v;
        }
    };
    auto loadB = [&](int k0) {
        #pragma unroll
        for (int j = 0; j < LB; j++) {
            int p  = t + j * 256;
            int kk = p & (BK - 1);
            int nn = p >> 4;
            int gn = n0 + nn, gk = k0 + kk;
            regB[j] = (gn < O && gk < K) ? Wt[(size_t)gn * K + gk] : 0.f;
        }
    };
    auto store = [&](int buf) {
        #pragma unroll
        for (int j = 0; j < CPT; j++) As[buf][acol0 + j][arow] = regA[j];
        #pragma unroll
        for (int j = 0; j < LB; j++) {
            int p = t + j * 256;
            Bs[buf][p & (BK - 1)][p >> 4] = regB[j];
        }
    };
    auto compute = [&](int buf) {
        #pragma unroll
        for (int k = 0; k < BK; k++) {
            float a[TM], b[TN];
            *(float4*)&a[0] = *(const float4*)&As[buf][k][ty * TM];
            *(float4*)&a[4] = *(const float4*)&As[buf][k][ty * TM + 4];
            *(float4*)&b[0] = *(const float4*)&Bs[buf][k][tx * TN];
            #pragma unroll
            for (int i = 0; i < TM; i++)
                #pragma unroll
                for (int j = 0; j < TN; j++)
                    acc[i][j] = fmaf(a[i], b[j], acc[i][j]);
        }
    };

    loadA(0); loadB(0);
    store(0);
    __syncthreads();
    int buf = 0;
    for (int k0 = 0; k0 < K; k0 += BK) {
        bool has_next = (k0 + BK) < K;
        if (has_next) { loadA(k0 + BK); loadB(k0 + BK); }
        compute(buf);
        if (has_next) {
            store(buf ^ 1);
            __syncthreads();
            buf ^= 1;
        }
    }

    #pragma unroll
    for (int i = 0; i < TM; i++) {
        int gm = m0 + ty * TM + i;
        if (gm >= M) continue;
        int w   = gm % W;
        int tmp = gm / W;
        int h   = tmp % Hout;
        int b   = tmp / Hout;
        #pragma unroll
        for (int j = 0; j < TN; j++) {
            int gn = n0 + tx * TN + j;
            if (gn >= O) continue;
            size_t idx = (((size_t)b * O + gn) * Hout + h) * W + w;
            float v = acc[i][j] + bias[gn];
            if (ACC) out[idx] = out[idx] + v;
            else     out[idx] = v;
        }
    }
}

// ===================== host-side dispatch =====================
static inline bool use_narrow(int N) {
    int c32 = ((N + 31) / 32) * 32;
    int c64 = ((N + 63) / 64) * 64;
    return c32 < c64;
}

static void run_lin(const float* A, const float* W, const float* b,
                    float* out, int M, int N, int K, bool relu)
{
    if (use_narrow(N)) {
        dim3 g((M + 255) / 256, (N + 31) / 32);
        if (relu) lin_kernel<256, 32, true ><<<g, 256>>>(A, W, b, out, M, N, K);
        else      lin_kernel<256, 32, false><<<g, 256>>>(A, W, b, out, M, N, K);
    } else {
        dim3 g((M + 127) / 128, (N + 63) / 64);
        if (relu) lin_kernel<128, 64, true ><<<g, 256>>>(A, W, b, out, M, N, K);
        else      lin_kernel<128, 64, false><<<g, 256>>>(A, W, b, out, M, N, K);
    }
}

template<int KH, bool ACC>
static void run_conv_t(const float* In, const float* W, const float* b,
                       float* out, int B, int I, int Hin, int Wd, int O, int pad)
{
    int Hout = Hin + 2 * pad - KH + 1;
    int M = B * Hout * Wd;
    if (use_narrow(O)) {
        dim3 g((M + 255) / 256, (O + 31) / 32);
        conv_kernel<256, 32, KH, ACC><<<g, 256>>>(In, W, b, out, B, I, Hin, Wd, O, pad);
    } else {
        dim3 g((M + 127) / 128, (O + 63) / 64);
        conv_kernel<128, 64, KH, ACC><<<g, 256>>>(In, W, b, out, B, I, Hin, Wd, O, pad);
    }
}

extern "C" void kernel_launch(void* const* d_in, const int* in_sizes, int n_in,
                              void* d_out, int out_size)
{
    const float* x   = (const float*)d_in[0];
    const float* W0a = (const float*)d_in[1];  const float* b0a = (const float*)d_in[2];
    const float* Wl0 = (const float*)d_in[3];  const float* bl0 = (const float*)d_in[4];
    const float* W0b = (const float*)d_in[5];  const float* b0b = (const float*)d_in[6];
    const float* Wr0 = (const float*)d_in[7];  const float* br0 = (const float*)d_in[8];
    const float* W0c = (const float*)d_in[9];  const float* b0c = (const float*)d_in[10];
    const float* W1  = (const float*)d_in[11]; const float* b1  = (const float*)d_in[12];
    const float* Wl1 = (const float*)d_in[13]; const float* bl1 = (const float*)d_in[14];
    const float* W2  = (const float*)d_in[15]; const float* b2  = (const float*)d_in[16];
    const float* Wra = (const float*)d_in[17]; const float* bra = (const float*)d_in[18];
    const float* Wa  = (const float*)d_in[19]; const float* ba  = (const float*)d_in[20];
    const float* W3  = (const float*)d_in[21]; const float* b3  = (const float*)d_in[22];
    const float* Wl2 = (const float*)d_in[23]; const float* bl2 = (const float*)d_in[24];
    const float* W4  = (const float*)d_in[25]; const float* b4  = (const float*)d_in[26];
    const float* Wrb = (const float*)d_in[27]; const float* brb = (const float*)d_in[28];
    const float* Wb  = (const float*)d_in[29]; const float* bb  = (const float*)d_in[30];

    float* out = (float*)d_out;

    float *S1, *S2, *S3;
    cudaGetSymbolAddress((void**)&S1, g_s1);
    cudaGetSymbolAddress((void**)&S2, g_s2);
    cudaGetSymbolAddress((void**)&S3, g_s3);

    const int B = 1024;

    // ---------------- block 0 ----------------
    run_conv_t<3, false>(x,  W0a, b0a, S1, B, 1, 5, 127, 5, 1);   // [B,5,5,127]
    run_lin(S1, Wl0, bl0, S2, B * 5 * 5, 81, 127, true);          // [B,5,5,81]
    run_conv_t<3, false>(S2, W0b, b0b, S3, B, 5, 5, 81, 25, 1);   // [B,25,5,81]
    run_lin(x,  Wr0, br0, S1, B * 1 * 5, 81, 127, false);         // [B,1,5,81]
    run_conv_t<1, true >(S1, W0c, b0c, S3, B, 1, 5, 81, 25, 0);   // x1 = S3

    // ---------------- block 1 ----------------
    run_conv_t<3, false>(S3, W1, b1, S1, B, 25, 5, 81, 75, 1);    // [B,75,5,81]
    run_lin(S1, Wl1, bl1, S2, B * 75 * 5, 41, 81, true);          // [B,75,5,41]
    run_conv_t<3, false>(S2, W2, b2, S1, B, 75, 5, 41, 150, 1);   // [B,150,5,41]
    run_lin(S3, Wra, bra, S2, B * 25 * 5, 41, 81, false);         // [B,25,5,41]
    run_conv_t<1, true >(S2, Wa, ba, S1, B, 25, 5, 41, 150, 0);   // x2 = S1

    // ---------------- block 2 ----------------
    run_conv_t<2, false>(S1, W3, b3, S3, B, 150, 5, 41, 300, 0);  // [B,300,4,41]
    run_lin(S3, Wl2, bl2, S2, B * 300 * 4, 18, 41, true);         // [B,300,4,18]
    run_conv_t<2, false>(S2, W4, b4, out, B, 300, 4, 18, 512, 0); // [B,512,3,18]
    run_lin(S1, Wrb, brb, S3, B * 150 * 5, 18, 41, false);        // [B,150,5,18]
    run_conv_t<3, true >(S3, Wb, bb, out, B, 150, 5, 18, 512, 0); // out += conv
}

// round 3
// speedup vs baseline: 1.6849x; 1.1308x over previous
#include <cuda_runtime.h>
#include <cstdint>

#define BK 16

// -------- scratch (device globals: allocation-free) --------
__device__ float g_s1[31500000];
__device__ float g_s2[22200000];
__device__ float g_s3[50400000];

// ===================== TF32 helpers =====================
__device__ __forceinline__ uint32_t f2tf32(float x) {
    uint32_t r;
    asm("cvt.rna.tf32.f32 %0, %1;" : "=r"(r) : "f"(x));
    return r;
}
__device__ __forceinline__ void mma_tf32(float* c, const uint32_t* a, const uint32_t* b) {
    asm volatile(
        "mma.sync.aligned.m16n8k8.row.col.f32.tf32.tf32.f32 "
        "{%0,%1,%2,%3}, {%4,%5,%6,%7}, {%8,%9}, {%0,%1,%2,%3};"
        : "+f"(c[0]), "+f"(c[1]), "+f"(c[2]), "+f"(c[3])
        : "r"(a[0]), "r"(a[1]), "r"(a[2]), "r"(a[3]), "r"(b[0]), "r"(b[1]));
}

// =====================================================================
// Tensor-core implicit-GEMM conv (3xTF32 for fp32-grade accuracy).
// in : [B, I, Hin, W], weight: [O, I, KH] == [O, K], out: [B, O, Hout, W]
// Block tile 128(M) x 64(N), BK=16, 8 warps (4x2), warp tile 32x32.
// =====================================================================
template<int KH, bool ACC>
__global__ __launch_bounds__(256)
void tc_conv(const float* __restrict__ In, const float* __restrict__ Wt,
             const float* __restrict__ bias, float* __restrict__ out,
             int B, int I, int Hin, int W, int O, int pad)
{
    constexpr int BM = 128, BN = 64;
    const int Hout = Hin + 2 * pad - KH + 1;
    const int M = B * Hout * W;
    const int K = I * KH;

    __shared__ __align__(16) float As[2][BK][BM + 4];
    __shared__ __align__(16) float Bs[2][BK][BN + 4];

    const int t    = threadIdx.x;
    const int m0   = blockIdx.x * BM;
    const int n0   = blockIdx.y * BN;
    const int warp = t >> 5;
    const int lane = t & 31;
    const int g    = lane >> 2;     // 0..7
    const int ctid = lane & 3;      // 0..3
    const int wm   = (warp & 3) * 32;
    const int wn   = (warp >> 2) * 32;

    // ---- A loader: fixed M-row per thread, 8 contiguous K elems ----
    const int arow  = t & (BM - 1);
    const int acol0 = (t >> 7) * 8;
    const int gm_l  = m0 + arow;
    const bool mvalid = gm_l < M;
    int lh = 0; size_t lbase = 0;
    if (mvalid) {
        int lw  = gm_l % W;
        int tmp = gm_l / W;
        lh = tmp % Hout;
        int lb = tmp / Hout;
        lbase = (size_t)lb * I * Hin * W + lw;
    }

    float regA[8], regB[4];
    float acc[2][4][4];
    #pragma unroll
    for (int mf = 0; mf < 2; mf++)
        #pragma unroll
        for (int nf = 0; nf < 4; nf++)
            #pragma unroll
            for (int i = 0; i < 4; i++) acc[mf][nf][i] = 0.f;

    auto loadA = [&](int k0) {
        #pragma unroll
        for (int j = 0; j < 8; j++) {
            int gk = k0 + acol0 + j;
            float v = 0.f;
            if (mvalid && gk < K) {
                int ii = gk / KH;
                int kh = gk - ii * KH;
                int hi = lh + kh - pad;
                if (hi >= 0 && hi < Hin)
                    v = In[lbase + (size_t)(ii * Hin + hi) * W];
            }
            regA[j] = v;
        }
    };
    auto loadB = [&](int k0) {
        #pragma unroll
        for (int j = 0; j < 4; j++) {
            int p  = t + j * 256;
            int kk = p & (BK - 1);
            int nn = p >> 4;
            int gn = n0 + nn, gk = k0 + kk;
            regB[j] = (gn < O && gk < K) ? Wt[(size_t)gn * K + gk] : 0.f;
        }
    };
    auto store = [&](int buf) {
        #pragma unroll
        for (int j = 0; j < 8; j++) As[buf][acol0 + j][arow] = regA[j];
        #pragma unroll
        for (int j = 0; j < 4; j++) {
            int p = t + j * 256;
            Bs[buf][p & (BK - 1)][p >> 4] = regB[j];
        }
    };
    auto compute = [&](int buf) {
        #pragma unroll
        for (int ks = 0; ks < 2; ks++) {
            const int kb = ks * 8;
            // A fragments (2 m16 frags) split hi/lo
            uint32_t ah[2][4], al[2][4];
            #pragma unroll
            for (int mf = 0; mf < 2; mf++) {
                float x0 = As[buf][kb + ctid    ][wm + mf * 16 + g    ];
                float x1 = As[buf][kb + ctid    ][wm + mf * 16 + g + 8];
                float x2 = As[buf][kb + ctid + 4][wm + mf * 16 + g    ];
                float x3 = As[buf][kb + ctid + 4][wm + mf * 16 + g + 8];
                ah[mf][0] = f2tf32(x0); al[mf][0] = f2tf32(x0 - __uint_as_float(ah[mf][0]));
                ah[mf][1] = f2tf32(x1); al[mf][1] = f2tf32(x1 - __uint_as_float(ah[mf][1]));
                ah[mf][2] = f2tf32(x2); al[mf][2] = f2tf32(x2 - __uint_as_float(ah[mf][2]));
                ah[mf][3] = f2tf32(x3); al[mf][3] = f2tf32(x3 - __uint_as_float(ah[mf][3]));
            }
            // B fragments (4 n8 frags) split hi/lo
            uint32_t bh[4][2], bl[4][2];
            #pragma unroll
            for (int nf = 0; nf < 4; nf++) {
                float y0 = Bs[buf][kb + ctid    ][wn + nf * 8 + g];
                float y1 = Bs[buf][kb + ctid + 4][wn + nf * 8 + g];
                bh[nf][0] = f2tf32(y0); bl[nf][0] = f2tf32(y0 - __uint_as_float(bh[nf][0]));
                bh[nf][1] = f2tf32(y1); bl[nf][1] = f2tf32(y1 - __uint_as_float(bh[nf][1]));
            }
            #pragma unroll
            for (int mf = 0; mf < 2; mf++)
                #pragma unroll
                for (int nf = 0; nf < 4; nf++) {
                    mma_tf32(acc[mf][nf], ah[mf], bh[nf]);
                    mma_tf32(acc[mf][nf], ah[mf], bl[nf]);
                    mma_tf32(acc[mf][nf], al[mf], bh[nf]);
                }
        }
    };

    loadA(0); loadB(0);
    store(0);
    __syncthreads();
    int buf = 0;
    for (int k0 = 0; k0 < K; k0 += BK) {
        bool has_next = (k0 + BK) < K;
        if (has_next) { loadA(k0 + BK); loadB(k0 + BK); }
        compute(buf);
        if (has_next) {
            store(buf ^ 1);
            __syncthreads();
            buf ^= 1;
        }
    }

    // ---- epilogue: scatter to NCHW ----
    #pragma unroll
    for (int mf = 0; mf < 2; mf++) {
        #pragma unroll
        for (int half = 0; half < 2; half++) {        // row g / g+8
            int gm = m0 + wm + mf * 16 + g + half * 8;
            if (gm >= M) continue;
            int w   = gm % W;
            int tmp = gm / W;
            int h   = tmp % Hout;
            int b   = tmp / Hout;
            size_t obase = (((size_t)b * O) * Hout + h) * W + w;
            size_t ostride = (size_t)Hout * W;
            #pragma unroll
            for (int nf = 0; nf < 4; nf++) {
                #pragma unroll
                for (int jj = 0; jj < 2; jj++) {
                    int gn = n0 + wn + nf * 8 + 2 * ctid + jj;
                    if (gn >= O) continue;
                    float v = acc[mf][nf][half * 2 + jj] + bias[gn];
                    size_t idx = obase + (size_t)gn * ostride;
                    if (ACC) out[idx] = out[idx] + v;
                    else     out[idx] = v;
                }
            }
        }
    }
}

// ===================== SIMT Linear (Semi_Linear) GEMM =====================
template<int BM_, int BN_, bool RELU>
__global__ __launch_bounds__(256, 2)
void lin_kernel(const float* __restrict__ A, const float* __restrict__ Wt,
                const float* __restrict__ bias, float* __restrict__ out,
                int M, int N, int K)
{
    constexpr int TM = 8, TN = 4;
    constexpr int GROUPS = 256 / BM_;
    constexpr int CPT    = BK / GROUPS;
    constexpr int LB     = BN_ * BK / 256;
    constexpr int NT     = BN_ / TN;

    __shared__ __align__(16) float As[2][BK][BM_];
    __shared__ __align__(16) float Bs[2][BK][BN_];

    const int t  = threadIdx.x;
    const int m0 = blockIdx.x * BM_;
    const int n0 = blockIdx.y * BN_;
    const int tx = t % NT;
    const int ty = t / NT;

    const int arow  = t % BM_;
    const int acol0 = (t / BM_) * CPT;
    const int gm_l  = m0 + arow;
    const bool mvalid = gm_l < M;
    const float* Arow = A + (size_t)gm_l * K;

    float regA[CPT], regB[LB];
    float acc[TM][TN];
    #pragma unroll
    for (int i = 0; i < TM; i++)
        #pragma unroll
        for (int j = 0; j < TN; j++) acc[i][j] = 0.f;

    auto loadA = [&](int k0) {
        #pragma unroll
        for (int j = 0; j < CPT; j++) {
            int gk = k0 + acol0 + j;
            regA[j] = (mvalid && gk < K) ? Arow[gk] : 0.f;
        }
    };
    auto loadB = [&](int k0) {
        #pragma unroll
        for (int j = 0; j < LB; j++) {
            int p  = t + j * 256;
            int kk = p & (BK - 1);
            int nn = p >> 4;
            int gn = n0 + nn, gk = k0 + kk;
            regB[j] = (gn < N && gk < K) ? Wt[(size_t)gn * K + gk] : 0.f;
        }
    };
    auto store = [&](int buf) {
        #pragma unroll
        for (int j = 0; j < CPT; j++) As[buf][acol0 + j][arow] = regA[j];
        #pragma unroll
        for (int j = 0; j < LB; j++) {
            int p = t + j * 256;
            Bs[buf][p & (BK - 1)][p >> 4] = regB[j];
        }
    };
    auto compute = [&](int buf) {
        #pragma unroll
        for (int k = 0; k < BK; k++) {
            float a[TM], b[TN];
            *(float4*)&a[0] = *(const float4*)&As[buf][k][ty * TM];
            *(float4*)&a[4] = *(const float4*)&As[buf][k][ty * TM + 4];
            *(float4*)&b[0] = *(const float4*)&Bs[buf][k][tx * TN];
            #pragma unroll
            for (int i = 0; i < TM; i++)
                #pragma unroll
                for (int j = 0; j < TN; j++)
                    acc[i][j] = fmaf(a[i], b[j], acc[i][j]);
        }
    };

    loadA(0); loadB(0);
    store(0);
    __syncthreads();
    int buf = 0;
    for (int k0 = 0; k0 < K; k0 += BK) {
        bool has_next = (k0 + BK) < K;
        if (has_next) { loadA(k0 + BK); loadB(k0 + BK); }
        compute(buf);
        if (has_next) {
            store(buf ^ 1);
            __syncthreads();
            buf ^= 1;
        }
    }

    #pragma unroll
    for (int i = 0; i < TM; i++) {
        int gm = m0 + ty * TM + i;
        if (gm >= M) continue;
        #pragma unroll
        for (int j = 0; j < TN; j++) {
            int gn = n0 + tx * TN + j;
            if (gn >= N) continue;
            float v = acc[i][j] + bias[gn];
            if (RELU) v = fmaxf(v, 0.f);
            out[(size_t)gm * N + gn] = v;
        }
    }
}

// ===================== SIMT conv (small layers) =====================
template<int BM_, int BN_, int KH, bool ACC>
__global__ __launch_bounds__(256, 2)
void conv_kernel(const float* __restrict__ In, const float* __restrict__ Wt,
                 const float* __restrict__ bias, float* __restrict__ out,
                 int B, int I, int Hin, int W, int O, int pad)
{
    constexpr int TM = 8, TN = 4;
    constexpr int GROUPS = 256 / BM_;
    constexpr int CPT    = BK / GROUPS;
    constexpr int LB     = BN_ * BK / 256;
    constexpr int NT     = BN_ / TN;

    const int Hout = Hin + 2 * pad - KH + 1;
    const int M = B * Hout * W;
    const int K = I * KH;

    __shared__ __align__(16) float As[2][BK][BM_];
    __shared__ __align__(16) float Bs[2][BK][BN_];

    const int t  = threadIdx.x;
    const int m0 = blockIdx.x * BM_;
    const int n0 = blockIdx.y * BN_;
    const int tx = t % NT;
    const int ty = t / NT;

    const int arow  = t % BM_;
    const int acol0 = (t / BM_) * CPT;
    const int gm_l  = m0 + arow;
    const bool mvalid = gm_l < M;
    int lh = 0; size_t lbase = 0;
    if (mvalid) {
        int lw  = gm_l % W;
        int tmp = gm_l / W;
        lh = tmp % Hout;
        int lb = tmp / Hout;
        lbase = (size_t)lb * I * Hin * W + lw;
    }

    float regA[CPT], regB[LB];
    float acc[TM][TN];
    #pragma unroll
    for (int i = 0; i < TM; i++)
        #pragma unroll
        for (int j = 0; j < TN; j++) acc[i][j] = 0.f;

    auto loadA = [&](int k0) {
        #pragma unroll
        for (int j = 0; j < CPT; j++) {
            int gk = k0 + acol0 + j;
            float v = 0.f;
            if (mvalid && gk < K) {
                int ii = gk / KH;
                int kh = gk - ii * KH;
                int hi = lh + kh - pad;
                if (hi >= 0 && hi < Hin)
                    v = In[lbase + (size_t)(ii * Hin + hi) * W];
            }
            regA[j] = v;
        }
    };
    auto loadB = [&](int k0) {
        #pragma unroll
        for (int j = 0; j < LB; j++) {
            int p  = t + j * 256;
            int kk = p & (BK - 1);
            int nn = p >> 4;
            int gn = n0 + nn, gk = k0 + kk;
            regB[j] = (gn < O && gk < K) ? Wt[(size_t)gn * K + gk] : 0.f;
        }
    };
    auto store = [&](int buf) {
        #pragma unroll
        for (int j = 0; j < CPT; j++) As[buf][acol0 + j][arow] = regA[j];
        #pragma unroll
        for (int j = 0; j < LB; j++) {
            int p = t + j * 256;
            Bs[buf][p & (BK - 1)][p >> 4] = regB[j];
        }
    };
    auto compute = [&](int buf) {
        #pragma unroll
        for (int k = 0; k < BK; k++) {
            float a[TM], b[TN];
            *(float4*)&a[0] = *(const float4*)&As[buf][k][ty * TM];
            *(float4*)&a[4] = *(const float4*)&As[buf][k][ty * TM + 4];
            *(float4*)&b[0] = *(const float4*)&Bs[buf][k][tx * TN];
            #pragma unroll
            for (int i = 0; i < TM; i++)
                #pragma unroll
                for (int j = 0; j < TN; j++)
                    acc[i][j] = fmaf(a[i], b[j], acc[i][j]);
        }
    };

    loadA(0); loadB(0);
    store(0);
    __syncthreads();
    int buf = 0;
    for (int k0 = 0; k0 < K; k0 += BK) {
        bool has_next = (k0 + BK) < K;
        if (has_next) { loadA(k0 + BK); loadB(k0 + BK); }
        compute(buf);
        if (has_next) {
            store(buf ^ 1);
            __syncthreads();
            buf ^= 1;
        }
    }

    #pragma unroll
    for (int i = 0; i < TM; i++) {
        int gm = m0 + ty * TM + i;
        if (gm >= M) continue;
        int w   = gm % W;
        int tmp = gm / W;
        int h   = tmp % Hout;
        int b   = tmp / Hout;
        #pragma unroll
        for (int j = 0; j < TN; j++) {
            int gn = n0 + tx * TN + j;
            if (gn >= O) continue;
            size_t idx = (((size_t)b * O + gn) * Hout + h) * W + w;
            float v = acc[i][j] + bias[gn];
            if (ACC) out[idx] = out[idx] + v;
            else     out[idx] = v;
        }
    }
}

// ===================== host-side dispatch =====================
static inline bool use_narrow(int N) {
    int c32 = ((N + 31) / 32) * 32;
    int c64 = ((N + 63) / 64) * 64;
    return c32 < c64;
}

static void run_lin(const float* A, const float* W, const float* b,
                    float* out, int M, int N, int K, bool relu)
{
    if (use_narrow(N)) {
        dim3 g((M + 255) / 256, (N + 31) / 32);
        if (relu) lin_kernel<256, 32, true ><<<g, 256>>>(A, W, b, out, M, N, K);
        else      lin_kernel<256, 32, false><<<g, 256>>>(A, W, b, out, M, N, K);
    } else {
        dim3 g((M + 127) / 128, (N + 63) / 64);
        if (relu) lin_kernel<128, 64, true ><<<g, 256>>>(A, W, b, out, M, N, K);
        else      lin_kernel<128, 64, false><<<g, 256>>>(A, W, b, out, M, N, K);
    }
}

template<int KH, bool ACC>
static void run_conv_simt(const float* In, const float* W, const float* b,
                          float* out, int B, int I, int Hin, int Wd, int O, int pad)
{
    int Hout = Hin + 2 * pad - KH + 1;
    int M = B * Hout * Wd;
    if (use_narrow(O)) {
        dim3 g((M + 255) / 256, (O + 31) / 32);
        conv_kernel<256, 32, KH, ACC><<<g, 256>>>(In, W, b, out, B, I, Hin, Wd, O, pad);
    } else {
        dim3 g((M + 127) / 128, (O + 63) / 64);
        conv_kernel<128, 64, KH, ACC><<<g, 256>>>(In, W, b, out, B, I, Hin, Wd, O, pad);
    }
}

template<int KH, bool ACC>
static void run_conv_tc(const float* In, const float* W, const float* b,
                        float* out, int B, int I, int Hin, int Wd, int O, int pad)
{
    int Hout = Hin + 2 * pad - KH + 1;
    int M = B * Hout * Wd;
    dim3 g((M + 127) / 128, (O + 63) / 64);
    tc_conv<KH, ACC><<<g, 256>>>(In, W, b, out, B, I, Hin, Wd, O, pad);
}

extern "C" void kernel_launch(void* const* d_in, const int* in_sizes, int n_in,
                              void* d_out, int out_size)
{
    const float* x   = (const float*)d_in[0];
    const float* W0a = (const float*)d_in[1];  const float* b0a = (const float*)d_in[2];
    const float* Wl0 = (const float*)d_in[3];  const float* bl0 = (const float*)d_in[4];
    const float* W0b = (const float*)d_in[5];  const float* b0b = (const float*)d_in[6];
    const float* Wr0 = (const float*)d_in[7];  const float* br0 = (const float*)d_in[8];
    const float* W0c = (const float*)d_in[9];  const float* b0c = (const float*)d_in[10];
    const float* W1  = (const float*)d_in[11]; const float* b1  = (const float*)d_in[12];
    const float* Wl1 = (const float*)d_in[13]; const float* bl1 = (const float*)d_in[14];
    const float* W2  = (const float*)d_in[15]; const float* b2  = (const float*)d_in[16];
    const float* Wra = (const float*)d_in[17]; const float* bra = (const float*)d_in[18];
    const float* Wa  = (const float*)d_in[19]; const float* ba  = (const float*)d_in[20];
    const float* W3  = (const float*)d_in[21]; const float* b3  = (const float*)d_in[22];
    const float* Wl2 = (const float*)d_in[23]; const float* bl2 = (const float*)d_in[24];
    const float* W4  = (const float*)d_in[25]; const float* b4  = (const float*)d_in[26];
    const float* Wrb = (const float*)d_in[27]; const float* brb = (const float*)d_in[28];
    const float* Wb  = (const float*)d_in[29]; const float* bb  = (const float*)d_in[30];

    float* out = (float*)d_out;

    float *S1, *S2, *S3;
    cudaGetSymbolAddress((void**)&S1, g_s1);
    cudaGetSymbolAddress((void**)&S2, g_s2);
    cudaGetSymbolAddress((void**)&S3, g_s3);

    const int B = 1024;

    // ---------------- block 0 (small: SIMT) ----------------
    run_conv_simt<3, false>(x,  W0a, b0a, S1, B, 1, 5, 127, 5, 1);   // [B,5,5,127]
    run_lin(S1, Wl0, bl0, S2, B * 5 * 5, 81, 127, true);             // [B,5,5,81]
    run_conv_simt<3, false>(S2, W0b, b0b, S3, B, 5, 5, 81, 25, 1);   // [B,25,5,81]
    run_lin(x,  Wr0, br0, S1, B * 1 * 5, 81, 127, false);            // [B,1,5,81]
    run_conv_simt<1, true >(S1, W0c, b0c, S3, B, 1, 5, 81, 25, 0);   // x1 = S3

    // ---------------- block 1 ----------------
    run_conv_tc  <3, false>(S3, W1, b1, S1, B, 25, 5, 81, 75, 1);    // [B,75,5,81]  TC
    run_lin(S1, Wl1, bl1, S2, B * 75 * 5, 41, 81, true);             // [B,75,5,41]
    run_conv_tc  <3, false>(S2, W2, b2, S1, B, 75, 5, 41, 150, 1);   // [B,150,5,41] TC
    run_lin(S3, Wra, bra, S2, B * 25 * 5, 41, 81, false);            // [B,25,5,41]
    run_conv_simt<1, true >(S2, Wa, ba, S1, B, 25, 5, 41, 150, 0);   // x2 = S1

    // ---------------- block 2 ----------------
    run_conv_tc  <2, false>(S1, W3, b3, S3, B, 150, 5, 41, 300, 0);  // [B,300,4,41] TC
    run_lin(S3, Wl2, bl2, S2, B * 300 * 4, 18, 41, true);            // [B,300,4,18]
    run_conv_tc  <2, false>(S2, W4, b4, out, B, 300, 4, 18, 512, 0); // [B,512,3,18] TC
    run_lin(S1, Wrb, brb, S3, B * 150 * 5, 18, 41, false);           // [B,150,5,18]
    run_conv_tc  <3, true >(S3, Wb, bb, out, B, 150, 5, 18, 512, 0); // out += conv TC
}